// round 11
// baseline (speedup 1.0000x reference)
#include <cuda_runtime.h>
#include <cuda_bf16.h>
#include <cstdint>

#define IN_F   256
#define OUT_F  64
#define MAX_NODES 100000
#define MAX_EDGES 1600000

// ---------------------------------------------------------------------------
// Device scratch (no allocation APIs allowed)
// ---------------------------------------------------------------------------
__device__ float g_support[(size_t)MAX_NODES * OUT_F];
__device__ unsigned long long g_bfrag[2 * 16 * 8 * 32];   // W mma fragments

// CSR build scratch
__device__ int   g_deg[MAX_NODES];        // per-row edge count (histogram)
__device__ int   g_rs[MAX_NODES];         // in-block exclusive scan
__device__ int   g_part[64];              // per-scan-block totals
__device__ int   g_row_start[MAX_NODES];  // final exclusive scan
__device__ int   g_slot[MAX_EDGES];       // within-row slot per edge (from hist)
__device__ int2  g_epack[MAX_EDGES];      // CSR packed {col, val_bits}

#define SCAN_T 512
#define SCAN_E 8
#define SCAN_CHUNK (SCAN_T * SCAN_E)      // 4096

// ---------------------------------------------------------------------------
// helpers
// ---------------------------------------------------------------------------
__device__ __forceinline__ uint32_t bfpack(float a, float b) {
    __nv_bfloat162 t = __floats2bfloat162_rn(a, b);
    return *reinterpret_cast<uint32_t*>(&t);
}
__device__ __forceinline__ void bfsplit(float v, float& hi, float& lo) {
    __nv_bfloat16 h = __float2bfloat16(v);
    hi = __bfloat162float(h);
    lo = v - hi;
}
__device__ __forceinline__ void split_pair(float vx, float vy,
                                           uint32_t& hp, uint32_t& lp) {
    hp = bfpack(vx, vy);
    float hx = __uint_as_float(hp << 16);
    float hy = __uint_as_float(hp & 0xffff0000u);
    lp = bfpack(vx - hx, vy - hy);
}
__device__ __forceinline__ void mma_bf16(float* c, const uint32_t* a,
                                         uint32_t b0, uint32_t b1) {
    asm volatile(
        "mma.sync.aligned.m16n8k16.row.col.f32.bf16.bf16.f32 "
        "{%0,%1,%2,%3}, {%4,%5,%6,%7}, {%8,%9}, {%0,%1,%2,%3};"
        : "+f"(c[0]), "+f"(c[1]), "+f"(c[2]), "+f"(c[3])
        : "r"(a[0]), "r"(a[1]), "r"(a[2]), "r"(a[3]), "r"(b0), "r"(b1));
}

// ---------------------------------------------------------------------------
// Kernel 0: pack W into per-lane B fragments (hi and lo bf16 images).
// ---------------------------------------------------------------------------
__global__ __launch_bounds__(256)
void prep_w_kernel(const float* __restrict__ w) {
    int idx = blockIdx.x * 256 + threadIdx.x;   // 0 .. 4095
    if (idx >= 16 * 8 * 32) return;
    int lane = idx & 31;
    int nt   = (idx >> 5) & 7;
    int ks   = idx >> 8;

    int col = nt * 8 + (lane >> 2);
    int r   = ks * 16 + (lane & 3) * 2;

    float v0 = w[(size_t)(r    ) * OUT_F + col];
    float v1 = w[(size_t)(r + 1) * OUT_F + col];
    float v2 = w[(size_t)(r + 8) * OUT_F + col];
    float v3 = w[(size_t)(r + 9) * OUT_F + col];

    float h0,l0,h1,l1,h2,l2,h3,l3;
    bfsplit(v0,h0,l0); bfsplit(v1,h1,l1); bfsplit(v2,h2,l2); bfsplit(v3,h3,l3);

    unsigned long long hi = (unsigned long long)bfpack(h0,h1)
                          | ((unsigned long long)bfpack(h2,h3) << 32);
    unsigned long long lo = (unsigned long long)bfpack(l0,l1)
                          | ((unsigned long long)bfpack(l2,l3) << 32);

    g_bfrag[idx]           = hi;
    g_bfrag[16*8*32 + idx] = lo;
}

// ---------------------------------------------------------------------------
// Kernel 1: GEMM via mma.sync bf16, 3-pass split precision (proven R5/R7)
// ---------------------------------------------------------------------------
__global__ __launch_bounds__(256)
void gemm_mma_kernel(const float* __restrict__ x,
                     float* __restrict__ support,
                     int n_nodes)
{
    extern __shared__ unsigned long long sm_bfrag[];   // 64 KB

    const int tid  = threadIdx.x;
    const int wid  = tid >> 5;
    const int lane = tid & 31;

    {
        const float4* src = reinterpret_cast<const float4*>(g_bfrag);
        float4* dst = reinterpret_cast<float4*>(sm_bfrag);
#pragma unroll
        for (int i = 0; i < 16; i++)
            dst[tid + i * 256] = src[tid + i * 256];
    }
    __syncthreads();

    const int row_base = blockIdx.x * 128 + wid * 16;
    int r0 = row_base + (lane >> 2);
    int r1 = r0 + 8;
    int r0c = (r0 < n_nodes) ? r0 : (n_nodes - 1);
    int r1c = (r1 < n_nodes) ? r1 : (n_nodes - 1);
    const float* xr0 = x + (size_t)r0c * IN_F;
    const float* xr1 = x + (size_t)r1c * IN_F;
    const int cbase = (lane & 3) * 2;

    float acc[8][4];
#pragma unroll
    for (int nt = 0; nt < 8; nt++)
#pragma unroll
        for (int j = 0; j < 4; j++) acc[nt][j] = 0.0f;

#pragma unroll 4
    for (int ks = 0; ks < 16; ks++) {
        int c0 = ks * 16 + cbase;
        float2 p00 = *reinterpret_cast<const float2*>(xr0 + c0);
        float2 p10 = *reinterpret_cast<const float2*>(xr1 + c0);
        float2 p01 = *reinterpret_cast<const float2*>(xr0 + c0 + 8);
        float2 p11 = *reinterpret_cast<const float2*>(xr1 + c0 + 8);

        uint32_t ahi[4], alo[4];
        split_pair(p00.x, p00.y, ahi[0], alo[0]);
        split_pair(p10.x, p10.y, ahi[1], alo[1]);
        split_pair(p01.x, p01.y, ahi[2], alo[2]);
        split_pair(p11.x, p11.y, ahi[3], alo[3]);

        const unsigned long long* bh = sm_bfrag + (size_t)ks * (8 * 32) + lane;
        unsigned long long bf[8];
#pragma unroll
        for (int nt = 0; nt < 8; nt++) bf[nt] = bh[nt * 32];
#pragma unroll
        for (int nt = 0; nt < 8; nt++) {
            uint32_t b0 = (uint32_t)bf[nt], b1 = (uint32_t)(bf[nt] >> 32);
            mma_bf16(acc[nt], ahi, b0, b1);
            mma_bf16(acc[nt], alo, b0, b1);
        }
        const unsigned long long* bl = bh + 16 * 8 * 32;
#pragma unroll
        for (int nt = 0; nt < 8; nt++) bf[nt] = bl[nt * 32];
#pragma unroll
        for (int nt = 0; nt < 8; nt++) {
            uint32_t b0 = (uint32_t)bf[nt], b1 = (uint32_t)(bf[nt] >> 32);
            mma_bf16(acc[nt], ahi, b0, b1);
        }
    }

    if (r0 < n_nodes) {
        float* d = support + (size_t)r0 * OUT_F + cbase;
#pragma unroll
        for (int nt = 0; nt < 8; nt++)
            *reinterpret_cast<float2*>(d + nt * 8) = make_float2(acc[nt][0], acc[nt][1]);
    }
    if (r1 < n_nodes) {
        float* d = support + (size_t)r1 * OUT_F + cbase;
#pragma unroll
        for (int nt = 0; nt < 8; nt++)
            *reinterpret_cast<float2*>(d + nt * 8) = make_float2(acc[nt][2], acc[nt][3]);
    }
}

// ---------------------------------------------------------------------------
// CSR build
// ---------------------------------------------------------------------------
// hist: 4 edges/thread, vector loads; record within-row slot per edge.
__global__ __launch_bounds__(256)
void hist_kernel(const int* __restrict__ adj_row, int n_edges) {
    int t = blockIdx.x * 256 + threadIdx.x;
    int base = t * 4;
    if (base + 4 <= n_edges) {
        int4 r4 = __ldg(reinterpret_cast<const int4*>(adj_row) + t);
        int4 s4;
        s4.x = atomicAdd(&g_deg[r4.x], 1);
        s4.y = atomicAdd(&g_deg[r4.y], 1);
        s4.z = atomicAdd(&g_deg[r4.z], 1);
        s4.w = atomicAdd(&g_deg[r4.w], 1);
        *(reinterpret_cast<int4*>(g_slot) + t) = s4;
    } else {
        for (int e = base; e < n_edges; e++)
            g_slot[e] = atomicAdd(&g_deg[adj_row[e]], 1);
    }
}

// scan1: per-block exclusive scan of deg into g_rs, block totals into g_part
__global__ __launch_bounds__(SCAN_T)
void scan1_kernel(int n) {
    __shared__ int s[SCAN_T];
    const int tid = threadIdx.x;
    const int base = blockIdx.x * SCAN_CHUNK + tid * SCAN_E;

    int c[SCAN_E];
    int tsum = 0;
#pragma unroll
    for (int j = 0; j < SCAN_E; j++) {
        int idx = base + j;
        c[j] = (idx < n) ? g_deg[idx] : 0;
        tsum += c[j];
    }
    s[tid] = tsum;
    __syncthreads();
    for (int off = 1; off < SCAN_T; off <<= 1) {
        int v = (tid >= off) ? s[tid - off] : 0;
        __syncthreads();
        s[tid] += v;
        __syncthreads();
    }
    int excl = s[tid] - tsum;
    if (tid == SCAN_T - 1) g_part[blockIdx.x] = s[tid];  // block total
#pragma unroll
    for (int j = 0; j < SCAN_E; j++) {
        int idx = base + j;
        if (idx < n) g_rs[idx] = excl;
        excl += c[j];
    }
}

// scan3: warp-scan the <=32 block totals inline, add offsets, write row_start.
__global__ __launch_bounds__(256)
void scan3_kernel(int n, int nblocks) {
    __shared__ int soff[32];
    int t = threadIdx.x;
    if (t < 32) {
        int orig = (t < nblocks) ? g_part[t] : 0;
        int v = orig;
#pragma unroll
        for (int o = 1; o < 32; o <<= 1) {
            int u = __shfl_up_sync(0xffffffff, v, o);
            if (t >= o) v += u;
        }
        soff[t] = v - orig;   // exclusive prefix
    }
    __syncthreads();
    int idx = blockIdx.x * 256 + t;
    if (idx < n)
        g_row_start[idx] = g_rs[idx] + soff[idx / SCAN_CHUNK];
}

// scatter: 4 edges/thread, no atomics. pos = row_start[row] + slot.
__global__ __launch_bounds__(256)
void scatter_kernel(const int* __restrict__ adj_row,
                    const int* __restrict__ adj_col,
                    const float* __restrict__ adj_vals,
                    int n_edges) {
    int t = blockIdx.x * 256 + threadIdx.x;
    int base = t * 4;
    if (base + 4 <= n_edges) {
        int4   r4 = __ldg(reinterpret_cast<const int4*>(adj_row) + t);
        int4   c4 = __ldg(reinterpret_cast<const int4*>(adj_col) + t);
        float4 v4 = __ldg(reinterpret_cast<const float4*>(adj_vals) + t);
        int4   s4 = *(reinterpret_cast<const int4*>(g_slot) + t);
        int p0 = __ldg(g_row_start + r4.x) + s4.x;
        int p1 = __ldg(g_row_start + r4.y) + s4.y;
        int p2 = __ldg(g_row_start + r4.z) + s4.z;
        int p3 = __ldg(g_row_start + r4.w) + s4.w;
        g_epack[p0] = make_int2(c4.x, __float_as_int(v4.x));
        g_epack[p1] = make_int2(c4.y, __float_as_int(v4.y));
        g_epack[p2] = make_int2(c4.z, __float_as_int(v4.z));
        g_epack[p3] = make_int2(c4.w, __float_as_int(v4.w));
    } else {
        for (int e = base; e < n_edges; e++) {
            int r = adj_row[e];
            int pos = __ldg(g_row_start + r) + g_slot[e];
            g_epack[pos] = make_int2(adj_col[e], __float_as_int(adj_vals[e]));
        }
    }
}

// ---------------------------------------------------------------------------
// spmm_csr: one warp per row, lane owns 2 cols (float2).
// Tail handled as ONE clamped batch of 8 (no serial latency chain).
// ---------------------------------------------------------------------------
__global__ __launch_bounds__(256)
void spmm_csr_kernel(const float* __restrict__ support,
                     const float* __restrict__ bias,
                     float* __restrict__ out,
                     int n_nodes)
{
    int w = (blockIdx.x * 256 + threadIdx.x) >> 5;
    int lane = threadIdx.x & 31;
    if (w >= n_nodes) return;

    int start = __ldg(g_row_start + w);
    int end   = start + __ldg(g_deg + w);

    float ax = 0.0f, ay = 0.0f;
    int e = start;
#pragma unroll 1
    for (; e + 8 <= end; e += 8) {
        int2 p[8]; float2 s[8];
#pragma unroll
        for (int j = 0; j < 8; j++) p[j] = __ldg(g_epack + e + j);
#pragma unroll
        for (int j = 0; j < 8; j++)
            s[j] = *reinterpret_cast<const float2*>(
                support + (size_t)p[j].x * OUT_F + lane * 2);
#pragma unroll
        for (int j = 0; j < 8; j++) {
            float v = __int_as_float(p[j].y);
            ax = fmaf(v, s[j].x, ax);
            ay = fmaf(v, s[j].y, ay);
        }
    }
    if (e < end) {
        // single clamped batch: invalid lanes read e (cached), contribute 0
        int2 p[8]; float2 s[8]; float v[8];
#pragma unroll
        for (int j = 0; j < 8; j++) {
            int idx = e + j;
            bool ok = idx < end;
            p[j] = __ldg(g_epack + (ok ? idx : e));
            v[j] = ok ? __int_as_float(p[j].y) : 0.0f;
        }
#pragma unroll
        for (int j = 0; j < 8; j++)
            s[j] = *reinterpret_cast<const float2*>(
                support + (size_t)p[j].x * OUT_F + lane * 2);
#pragma unroll
        for (int j = 0; j < 8; j++) {
            ax = fmaf(v[j], s[j].x, ax);
            ay = fmaf(v[j], s[j].y, ay);
        }
    }

    float2 bv = *reinterpret_cast<const float2*>(bias + lane * 2);
    *reinterpret_cast<float2*>(out + (size_t)w * OUT_F + lane * 2) =
        make_float2(ax + bv.x, ay + bv.y);
}

// ---------------------------------------------------------------------------
// Launch.  Inputs (metadata order): x, adj_row, adj_col, adj_vals, weight, b
// Fork/join: CSR build (side stream) overlaps prep_w + GEMM (stream 0).
// ---------------------------------------------------------------------------
extern "C" void kernel_launch(void* const* d_in, const int* in_sizes, int n_in,
                              void* d_out, int out_size)
{
    const float* x        = (const float*)d_in[0];
    const int*   adj_row  = (const int*)  d_in[1];
    const int*   adj_col  = (const int*)  d_in[2];
    const float* adj_vals = (const float*)d_in[3];
    const float* weight   = (const float*)d_in[4];
    const float* b        = (const float*)d_in[5];
    float* out = (float*)d_out;

    const int n_nodes = in_sizes[0] / IN_F;
    const int n_edges = in_sizes[1];

    float* support = nullptr;
    cudaGetSymbolAddress((void**)&support, g_support);
    void* degp = nullptr;
    cudaGetSymbolAddress(&degp, g_deg);

    cudaFuncSetAttribute(gemm_mma_kernel,
                         cudaFuncAttributeMaxDynamicSharedMemorySize, 65536);

    const int e4b = (n_edges / 4 + 255) / 256;           // 4 edges per thread
    const int nscan = (n_nodes + SCAN_CHUNK - 1) / SCAN_CHUNK;

    static cudaStream_t s2 = nullptr;
    static cudaEvent_t evFork = nullptr, evJoin = nullptr;
    if (!s2) {
        cudaStreamCreateWithFlags(&s2, cudaStreamNonBlocking);
        cudaEventCreateWithFlags(&evFork, cudaEventDisableTiming);
        cudaEventCreateWithFlags(&evJoin, cudaEventDisableTiming);
    }

    // ---- fork: CSR build on s2
    cudaEventRecord(evFork, 0);
    cudaStreamWaitEvent(s2, evFork, 0);

    cudaMemsetAsync(degp, 0, (size_t)n_nodes * sizeof(int), s2);
    hist_kernel<<<e4b, 256, 0, s2>>>(adj_row, n_edges);
    scan1_kernel<<<nscan, SCAN_T, 0, s2>>>(n_nodes);
    scan3_kernel<<<(n_nodes + 255) / 256, 256, 0, s2>>>(n_nodes, nscan);
    scatter_kernel<<<e4b, 256, 0, s2>>>(adj_row, adj_col, adj_vals, n_edges);

    // ---- stream 0: W pack + GEMM (independent of CSR build)
    prep_w_kernel<<<16, 256>>>(weight);
    int gemm_blocks = (n_nodes + 127) / 128;
    gemm_mma_kernel<<<gemm_blocks, 256, 65536>>>(x, support, n_nodes);

    // ---- join
    cudaEventRecord(evJoin, s2);
    cudaStreamWaitEvent(0, evJoin, 0);

    // ---- SpMM over CSR, bias folded in
    int blocks = (n_nodes * 32 + 255) / 256;
    spmm_csr_kernel<<<blocks, 256>>>(support, b, out, n_nodes);
}